// round 1
// baseline (speedup 1.0000x reference)
#include <cuda_runtime.h>
#include <math_constants.h>
#include <cstdint>

#define BB 1024
#define LL 256
#define DD 64
#define TDIM 100
#define NTHR 64        // number of relu thresholds
#define NINT 65        // intervals = NTHR + 1
#define MSTRIDE 66     // padded m-stride for bank-conflict avoidance

// Scratch (no allocations allowed): threshold table + piecewise-linear table.
__device__ float  g_T[NTHR];
__device__ float2 g_UV[DD * MSTRIDE];   // [j][m] : (U, V)

// ---------------------------------------------------------------------------
// Kernel 1: compute relu crossing thresholds t_k = -b1_k / w1_k (only where a
// sign change happens for x >= 0), rank-sort ascending into g_T (INF padded).
// ---------------------------------------------------------------------------
__global__ void build_T_kernel(const float* __restrict__ w1,
                               const float* __restrict__ b1) {
    int k = threadIdx.x;  // 0..63
    float w = w1[k], b = b1[k];
    bool crossing = (w > 0.0f && b < 0.0f) || (w < 0.0f && b > 0.0f);
    float t = crossing ? (-b / w) : CUDART_INF_F;

    __shared__ float sT[NTHR];
    sT[k] = t;
    __syncthreads();

    int rank = 0;
    #pragma unroll
    for (int j = 0; j < NTHR; ++j) {
        float tj = sT[j];
        rank += (tj < t) || (tj == t && j < k);   // INF==INF ties broken by index
    }
    g_T[rank] = t;
}

// ---------------------------------------------------------------------------
// Kernel 2: for each interval m (between sorted thresholds), evaluate the relu
// active mask at the interval midpoint and accumulate
//   U_m[j] = sum_{k active} w1_k * w2[k][j]
//   V_m[j] = sum_{k active} b1_k * w2[k][j]
// Stored transposed [j][m] (stride 66) -> divergent-m LDS is <=2-way conflict.
// ---------------------------------------------------------------------------
__global__ void build_UV_kernel(const float* __restrict__ w1,
                                const float* __restrict__ b1,
                                const float* __restrict__ w2) {
    int m = blockIdx.x;    // 0..64
    int j = threadIdx.x;   // 0..63

    float lo = (m == 0)        ? 0.0f         : g_T[m - 1];
    float hi = (m == NINT - 1) ? CUDART_INF_F : g_T[m];
    float mid;
    if (!isfinite(lo))      mid = 1.0f;              // unreachable row
    else if (!isfinite(hi)) mid = lo * 2.0f + 1.0f;  // last reachable interval
    else                    mid = 0.5f * (lo + hi);

    float U = 0.0f, V = 0.0f;
    #pragma unroll 4
    for (int k = 0; k < NTHR; ++k) {
        float w = w1[k], b = b1[k];
        if (fmaf(mid, w, b) > 0.0f) {
            float w2kj = w2[k * DD + j];
            U = fmaf(w, w2kj, U);
            V = fmaf(b, w2kj, V);
        }
    }
    g_UV[j * MSTRIDE + m] = make_float2(U, V);
}

// ---------------------------------------------------------------------------
// Main fused kernel: one block per batch row b, one thread per position i.
//  1. pairwise-equality counts (replaces the 20000-wide histogram + gather)
//  2. LTF time weight: sigmoid( sum_k cos(t*w_k+b_k)*wts_k + bts )
//  3. piecewise-linear MLP: out = x0*U[m0] + V[m0] + x1*U[m1] + V[m1] + 2*b2
// ---------------------------------------------------------------------------
__global__ __launch_bounds__(LL) void tni_main_kernel(
    const int*   __restrict__ src_ids,
    const int*   __restrict__ dst_ids,
    const float* __restrict__ src_times,
    const float* __restrict__ dst_times,
    const float* __restrict__ node_times,
    const float* __restrict__ w_time,
    const float* __restrict__ b_time,
    const float* __restrict__ w_ts,
    const float* __restrict__ b_ts,
    const float* __restrict__ b2,
    float*       __restrict__ out)
{
    __shared__ int2   sids[LL];                  // (src_id, dst_id) per position
    __shared__ float  swt[TDIM], sbt[TDIM], swts[TDIM];
    __shared__ float  sT[NTHR];
    __shared__ float  sb2[DD];
    __shared__ float2 sUV[DD * MSTRIDE];         // 33.8 KB

    const int b = blockIdx.x;
    const int i = threadIdx.x;

    const int sid = src_ids[b * LL + i];
    const int did = dst_ids[b * LL + i];
    sids[i] = make_int2(sid, did);

    for (int t = i; t < TDIM; t += LL) {
        swt[t]  = w_time[t];
        sbt[t]  = b_time[t];
        swts[t] = w_ts[t];
    }
    if (i < NTHR) sT[i]  = g_T[i];
    if (i < DD)   sb2[i] = b2[i];
    for (int t = i; t < DD * MSTRIDE; t += LL) sUV[t] = g_UV[t];
    __syncthreads();

    // ---- 1. pairwise counts ----
    int css = 0, csd = 0, cds = 0, cdd = 0;
    #pragma unroll 8
    for (int j = 0; j < LL; ++j) {
        int2 p = sids[j];
        css += (p.x == sid);
        csd += (p.y == sid);
        cds += (p.x == did);
        cdd += (p.y == did);
    }
    if (sid == 0) { css = 0; csd = 0; }
    if (did == 0) { cds = 0; cdd = 0; }

    // ---- 2. time weights ----
    const float nt  = node_times[b];
    const float tds = nt - src_times[b * LL + i];
    const float tdd = nt - dst_times[b * LL + i];
    float accs = 0.0f, accd = 0.0f;
    #pragma unroll 4
    for (int k = 0; k < TDIM; ++k) {
        float w  = swt[k];
        float bt = sbt[k];
        float wo = swts[k];
        accs = fmaf(__cosf(fmaf(tds, w, bt)), wo, accs);
        accd = fmaf(__cosf(fmaf(tdd, w, bt)), wo, accd);
    }
    const float bts = b_ts[0];
    const float sw = 1.0f / (1.0f + __expf(-(accs + bts)));
    const float dw = 1.0f / (1.0f + __expf(-(accd + bts)));

    const float x_ss = (float)css * sw;
    const float x_sd = (float)csd * sw;
    const float x_ds = (float)cds * dw;
    const float x_dd = (float)cdd * dw;

    // ---- interval classification: m(x) = #{ T_j < x } ----
    int m_ss = 0, m_sd = 0, m_ds = 0, m_dd = 0;
    #pragma unroll
    for (int j = 0; j < NTHR; ++j) {
        float t = sT[j];
        m_ss += (t < x_ss);
        m_sd += (t < x_sd);
        m_ds += (t < x_ds);
        m_dd += (t < x_dd);
    }

    // ---- 3. epilogue: gather U/V, fma, vectorized stores ----
    const size_t base = ((size_t)b * LL + i) * DD;
    float4* __restrict__ outs = (float4*)(out + base);
    float4* __restrict__ outd = (float4*)(out + (size_t)BB * LL * DD + base);

    #pragma unroll
    for (int j4 = 0; j4 < DD / 4; ++j4) {
        float4 rs, rd;
        float* ps = &rs.x;
        float* pd = &rd.x;
        #pragma unroll
        for (int q = 0; q < 4; ++q) {
            int j = j4 * 4 + q;
            float2 uv0 = sUV[j * MSTRIDE + m_ss];
            float2 uv1 = sUV[j * MSTRIDE + m_sd];
            float2 uv2 = sUV[j * MSTRIDE + m_ds];
            float2 uv3 = sUV[j * MSTRIDE + m_dd];
            float bb2 = 2.0f * sb2[j];
            ps[q] = fmaf(x_ss, uv0.x, uv0.y) + fmaf(x_sd, uv1.x, uv1.y) + bb2;
            pd[q] = fmaf(x_ds, uv2.x, uv2.y) + fmaf(x_dd, uv3.x, uv3.y) + bb2;
        }
        outs[j4] = rs;
        outd[j4] = rd;
    }
}

// ---------------------------------------------------------------------------
// Input order (metadata): 0 src_ids, 1 dst_ids, 2 src_times, 3 dst_times,
// 4 node_times, 5 num_nodes (unused), 6 w_time, 7 b_time, 8 w_ts, 9 b_ts,
// 10 w1, 11 b1, 12 w2, 13 b2.  Output: [src_feats (B,L,D); dst_feats (B,L,D)].
// ---------------------------------------------------------------------------
extern "C" void kernel_launch(void* const* d_in, const int* in_sizes, int n_in,
                              void* d_out, int out_size) {
    const int*   src_ids    = (const int*)  d_in[0];
    const int*   dst_ids    = (const int*)  d_in[1];
    const float* src_times  = (const float*)d_in[2];
    const float* dst_times  = (const float*)d_in[3];
    const float* node_times = (const float*)d_in[4];
    const float* w_time     = (const float*)d_in[6];
    const float* b_time     = (const float*)d_in[7];
    const float* w_ts       = (const float*)d_in[8];
    const float* b_ts       = (const float*)d_in[9];
    const float* w1         = (const float*)d_in[10];
    const float* b1         = (const float*)d_in[11];
    const float* w2         = (const float*)d_in[12];
    const float* b2         = (const float*)d_in[13];
    float*       out        = (float*)d_out;

    build_T_kernel<<<1, NTHR>>>(w1, b1);
    build_UV_kernel<<<NINT, DD>>>(w1, b1, w2);
    tni_main_kernel<<<BB, LL>>>(src_ids, dst_ids, src_times, dst_times,
                                node_times, w_time, b_time, w_ts, b_ts,
                                b2, out);
}

// round 3
// speedup vs baseline: 1.6501x; 1.6501x over previous
#include <cuda_runtime.h>
#include <math_constants.h>
#include <cstdint>

#define BB 1024
#define LL 256
#define DD 64
#define TDIM 100
#define NTHR 64
#define NINT 65
#define NT 1024          // weight-table intervals (table has NT+1 entries)

// Scratch in __device__ globals (no allocations allowed).
__device__ float  g_T[NTHR];            // sorted relu thresholds (INF padded)
__device__ float2 g_UV2[NINT * DD];     // [m][j] : (U, V)
__device__ float  g_W[NT + 1];          // weight(t) lookup table over t in [0,2]

// ---------------------------------------------------------------------------
// Setup kernel (single launch):
//   blocks 0..64 : rank-sort thresholds locally, emit UV row m=blockIdx.x
//                  (block 0 also publishes g_T)
//   blocks 65..69: tabulate weight(t) = sigmoid(sum_k cos(t*w_k+b_k)*wts_k + bts)
// ---------------------------------------------------------------------------
__global__ void setup_kernel(const float* __restrict__ w1,
                             const float* __restrict__ b1,
                             const float* __restrict__ w2,
                             const float* __restrict__ w_time,
                             const float* __restrict__ b_time,
                             const float* __restrict__ w_ts,
                             const float* __restrict__ b_ts) {
    int blk = blockIdx.x;
    if (blk < NINT) {
        __shared__ float sTin[NTHR], sTs[NTHR];
        int k = threadIdx.x;
        float t = CUDART_INF_F;
        if (k < NTHR) {
            float w = w1[k], b = b1[k];
            bool crossing = (w > 0.0f && b < 0.0f) || (w < 0.0f && b > 0.0f);
            t = crossing ? (-b / w) : CUDART_INF_F;
            sTin[k] = t;
        }
        __syncthreads();
        if (k < NTHR) {
            int rank = 0;
            #pragma unroll
            for (int j = 0; j < NTHR; ++j) {
                float tj = sTin[j];
                rank += (tj < t) || (tj == t && j < k);
            }
            sTs[rank] = t;
        }
        __syncthreads();
        if (blk == 0 && k < NTHR) g_T[k] = sTs[k];

        int m = blk;
        float lo = (m == 0)        ? 0.0f         : sTs[m - 1];
        float hi = (m == NINT - 1) ? CUDART_INF_F : sTs[m];
        float mid;
        if (!isfinite(lo))      mid = 1.0f;              // unreachable row
        else if (!isfinite(hi)) mid = lo * 2.0f + 1.0f;  // last reachable interval
        else                    mid = 0.5f * (lo + hi);

        if (k < DD) {
            float U = 0.0f, V = 0.0f;
            #pragma unroll 4
            for (int k2 = 0; k2 < NTHR; ++k2) {
                float w = w1[k2], b = b1[k2];
                if (fmaf(mid, w, b) > 0.0f) {
                    float w2v = w2[k2 * DD + k];
                    U = fmaf(w, w2v, U);
                    V = fmaf(b, w2v, V);
                }
            }
            g_UV2[m * DD + k] = make_float2(U, V);
        }
    } else {
        int g = (blk - NINT) * blockDim.x + threadIdx.x;
        if (g <= NT) {
            float t = (float)g * (2.0f / (float)NT);
            float acc = b_ts[0];
            for (int k = 0; k < TDIM; ++k)
                acc += cosf(fmaf(t, w_time[k], b_time[k])) * w_ts[k];
            g_W[g] = 1.0f / (1.0f + expf(-acc));
        }
    }
}

// ---------------------------------------------------------------------------
// Main kernel helpers
// ---------------------------------------------------------------------------
__device__ __forceinline__ unsigned hash_id(int id) {
    return ((unsigned)id * 2654435761u) >> 23;  // 9 bits -> [0,512)
}

__device__ __forceinline__ void hash_insert(int* keys, int* cnts, int base, int id) {
    if (id == 0) return;
    unsigned slot = hash_id(id) & 511u;
    while (true) {
        int prev = atomicCAS(&keys[base + slot], 0, id);
        if (prev == 0 || prev == id) { atomicAdd(&cnts[base + slot], 1); break; }
        slot = (slot + 1) & 511u;
    }
}

__device__ __forceinline__ int hash_lookup(const int* keys, const int* cnts,
                                           int base, int id) {
    if (id == 0) return 0;
    unsigned slot = hash_id(id) & 511u;
    while (true) {
        int k = keys[base + slot];
        if (k == id) return cnts[base + slot];
        if (k == 0) return 0;
        slot = (slot + 1) & 511u;
    }
}

__device__ __forceinline__ float weight_lookup(float t) {
    float u = t * ((float)NT * 0.5f);               // 1/h = NT/2
    u = fminf(fmaxf(u, 0.0f), (float)NT - 0.001f);  // safety clamp
    int i0 = (int)u;
    float f = u - (float)i0;
    float a  = __ldg(&g_W[i0]);
    float bb = __ldg(&g_W[i0 + 1]);
    return fmaf(f, bb - a, a);
}

// ---------------------------------------------------------------------------
// Main fused kernel. One block per batch row.
// Phase A (thread-per-position): hash counts, table time-weights, x & interval m.
// Phase B (warp-cooperative): lanes sweep j for one position at a time ->
//   conflict-free coalesced LDS.128 row reads + coalesced STG.
// ---------------------------------------------------------------------------
__global__ __launch_bounds__(LL, 5) void tni_main_kernel(
    const int*   __restrict__ src_ids,
    const int*   __restrict__ dst_ids,
    const float* __restrict__ src_times,
    const float* __restrict__ dst_times,
    const float* __restrict__ node_times,
    const float* __restrict__ b2,
    float*       __restrict__ out)
{
    __shared__ float2 sUV[NINT * DD];          // 33,280 B, layout [m][j]
    __shared__ __align__(16) int sHash[2048];  // keys [0..1023], counts [1024..2047]
                                               // reused later: sx (float4[256]) | sm (int[256])
    __shared__ float sTm[NTHR];

    const int b = blockIdx.x;
    const int i = threadIdx.x;

    // --- preamble: UV table to shared, hash init, thresholds ---
    {
        const float4* srcv = (const float4*)g_UV2;   // 2080 float4
        float4* dstv = (float4*)sUV;
        #pragma unroll
        for (int t = 0; t < 8; ++t) {
            int idx = i + t * LL;
            if (idx < (NINT * DD) / 2) dstv[idx] = srcv[idx];
        }
    }
    #pragma unroll
    for (int t = 0; t < 8; ++t) sHash[i + t * LL] = 0;
    if (i < NTHR) sTm[i] = g_T[i];

    const int sid = src_ids[b * LL + i];
    const int did = dst_ids[b * LL + i];
    __syncthreads();

    // --- hash histogram inserts ---
    int* keys = sHash;
    int* cnts = sHash + 1024;
    hash_insert(keys, cnts, 0,   sid);
    hash_insert(keys, cnts, 512, did);
    __syncthreads();

    // --- lookups ---
    const int css = hash_lookup(keys, cnts, 0,   sid);
    const int csd = hash_lookup(keys, cnts, 512, sid);
    const int cds = hash_lookup(keys, cnts, 0,   did);
    const int cdd = hash_lookup(keys, cnts, 512, did);

    // --- time weights via 1-D lerp table ---
    const float nt = node_times[b];
    const float ws = weight_lookup(nt - src_times[b * LL + i]);
    const float wd = weight_lookup(nt - dst_times[b * LL + i]);

    const float x_ss = (float)css * ws;
    const float x_sd = (float)csd * ws;
    const float x_ds = (float)cds * wd;
    const float x_dd = (float)cdd * wd;

    // --- interval index via branchless binary search (m = #{T < x}) ---
    int m_ss = 0, m_sd = 0, m_ds = 0, m_dd = 0;
    #pragma unroll
    for (int s = 32; s >= 1; s >>= 1) {
        if (sTm[m_ss + s - 1] < x_ss) m_ss += s;
        if (sTm[m_sd + s - 1] < x_sd) m_sd += s;
        if (sTm[m_ds + s - 1] < x_ds) m_ds += s;
        if (sTm[m_dd + s - 1] < x_dd) m_dd += s;
    }
    if (sTm[m_ss] < x_ss) ++m_ss;
    if (sTm[m_sd] < x_sd) ++m_sd;
    if (sTm[m_ds] < x_ds) ++m_ds;
    if (sTm[m_dd] < x_dd) ++m_dd;

    __syncthreads();  // all hash lookups done; reuse sHash region

    float4* sx = (float4*)sHash;           // 4 KB
    int*    smv = sHash + 1024;            // 1 KB used
    sx[i]  = make_float4(x_ss, x_sd, x_ds, x_dd);
    smv[i] = m_ss | (m_sd << 8) | (m_ds << 16) | (m_dd << 24);
    __syncthreads();

    // --- Phase B: warp-cooperative epilogue ---
    const int wid  = i >> 5;
    const int lane = i & 31;

    const float2 b2v = __ldg(&((const float2*)b2)[lane]);  // j = 2*lane, 2*lane+1
    const float tb0 = 2.0f * b2v.x;
    const float tb1 = 2.0f * b2v.y;

    const float4* UV = (const float4*)sUV;  // row m: 32 float4s; idx = m*32 + lane
    const size_t dst_off = (size_t)BB * LL * DD;
    float* __restrict__ outp = out;

    #pragma unroll 2
    for (int p0 = 0; p0 < 32; ++p0) {
        const int p = (wid << 5) | p0;
        const float4 xv = sx[p];      // broadcast
        const int mm = smv[p];        // broadcast
        const int ma = mm & 255;
        const int mb = (mm >> 8) & 255;
        const int mc = (mm >> 16) & 255;
        const int md = (mm >> 24) & 255;

        const float4 A = UV[ma * 32 + lane];
        const float4 Bv = UV[mb * 32 + lane];
        const float4 C = UV[mc * 32 + lane];
        const float4 Dv = UV[md * 32 + lane];

        float2 rs, rd;
        rs.x = fmaf(xv.x, A.x, A.y) + fmaf(xv.y, Bv.x, Bv.y) + tb0;
        rs.y = fmaf(xv.x, A.z, A.w) + fmaf(xv.y, Bv.z, Bv.w) + tb1;
        rd.x = fmaf(xv.z, C.x, C.y) + fmaf(xv.w, Dv.x, Dv.y) + tb0;
        rd.y = fmaf(xv.z, C.z, C.w) + fmaf(xv.w, Dv.z, Dv.w) + tb1;

        const size_t rowbase = (((size_t)b * LL + p) * DD) + 2 * lane;
        *(float2*)(outp + rowbase)           = rs;
        *(float2*)(outp + dst_off + rowbase) = rd;
    }
}

// ---------------------------------------------------------------------------
// Inputs: 0 src_ids, 1 dst_ids, 2 src_times, 3 dst_times, 4 node_times,
// 5 num_nodes (unused), 6 w_time, 7 b_time, 8 w_ts, 9 b_ts, 10 w1, 11 b1,
// 12 w2, 13 b2.  Output: [src_feats (B,L,D); dst_feats (B,L,D)].
// ---------------------------------------------------------------------------
extern "C" void kernel_launch(void* const* d_in, const int* in_sizes, int n_in,
                              void* d_out, int out_size) {
    const int*   src_ids    = (const int*)  d_in[0];
    const int*   dst_ids    = (const int*)  d_in[1];
    const float* src_times  = (const float*)d_in[2];
    const float* dst_times  = (const float*)d_in[3];
    const float* node_times = (const float*)d_in[4];
    const float* w_time     = (const float*)d_in[6];
    const float* b_time     = (const float*)d_in[7];
    const float* w_ts       = (const float*)d_in[8];
    const float* b_ts       = (const float*)d_in[9];
    const float* w1         = (const float*)d_in[10];
    const float* b1         = (const float*)d_in[11];
    const float* w2         = (const float*)d_in[12];
    const float* b2         = (const float*)d_in[13];
    float*       out        = (float*)d_out;

    const int wt_blocks = (NT + 1 + 255) / 256;   // 5
    setup_kernel<<<NINT + wt_blocks, 256>>>(w1, b1, w2, w_time, b_time, w_ts, b_ts);
    tni_main_kernel<<<BB, LL>>>(src_ids, dst_ids, src_times, dst_times,
                                node_times, b2, out);
}